// round 12
// baseline (speedup 1.0000x reference)
#include <cuda_runtime.h>
#include <cuda_bf16.h>
#include <cuda_fp16.h>
#include <cstdint>

#define NTR 8192
#define NT  8192
#define DIN 1024
#define LD  64
#define DY  128

// ---------------------------------------------------------------------------
// device scratch (no allocations allowed)
// ---------------------------------------------------------------------------
__device__ float g_Q[(size_t)NT * LD];
__device__ float g_K[(size_t)NTR * LD];
__device__ float g_muA[LD];
__device__ __nv_bfloat16 g_Ah[(size_t)DIN * LD];
__device__ __nv_bfloat16 g_Al[(size_t)DIN * LD];
__device__ __nv_bfloat16 g_Qh[(size_t)NT * LD];
__device__ __nv_bfloat16 g_Ql[(size_t)NT * LD];
__device__ __nv_bfloat16 g_Kh[(size_t)NTR * LD];
__device__ __nv_bfloat16 g_Kl[(size_t)NTR * LD];
__device__ __half g_Vf[(size_t)NTR * DY];
__device__ float g_Opart[2 * (size_t)NT * DY];
__device__ float g_lpart[2 * (size_t)NT];
__device__ float g_mpart[2 * (size_t)NT];

// ---------------------------------------------------------------------------
// helpers (portable PTX only: sm_80-level mma/ldmatrix/cp.async)
// ---------------------------------------------------------------------------
__device__ __forceinline__ uint32_t smem_u32(const void* p) {
    uint32_t a;
    asm("{ .reg .u64 t; cvta.to.shared.u64 t, %1; cvt.u32.u64 %0, t; }"
        : "=r"(a) : "l"(p));
    return a;
}

__device__ __forceinline__ void cp16(uint32_t dst, const void* src) {
    asm volatile("cp.async.cg.shared.global [%0], [%1], 16;"
                 :: "r"(dst), "l"(src));
}
#define CP_COMMIT asm volatile("cp.async.commit_group;" ::: "memory")
#define CP_WAIT0  asm volatile("cp.async.wait_group 0;" ::: "memory")
#define CP_WAIT1  asm volatile("cp.async.wait_group 1;" ::: "memory")

__device__ __forceinline__ void ldsm_x4(uint32_t* r, uint32_t a) {
    asm volatile("ldmatrix.sync.aligned.m8n8.x4.shared.b16 {%0,%1,%2,%3}, [%4];"
                 : "=r"(r[0]), "=r"(r[1]), "=r"(r[2]), "=r"(r[3]) : "r"(a));
}
__device__ __forceinline__ void ldsm_x4t(uint32_t* r, uint32_t a) {
    asm volatile("ldmatrix.sync.aligned.m8n8.x4.trans.shared.b16 {%0,%1,%2,%3}, [%4];"
                 : "=r"(r[0]), "=r"(r[1]), "=r"(r[2]), "=r"(r[3]) : "r"(a));
}
__device__ __forceinline__ void mma_bf16(float* c, const uint32_t* a,
                                         uint32_t b0, uint32_t b1) {
    asm volatile(
        "mma.sync.aligned.m16n8k16.row.col.f32.bf16.bf16.f32 "
        "{%0,%1,%2,%3}, {%4,%5,%6,%7}, {%8,%9}, {%0,%1,%2,%3};"
        : "+f"(c[0]), "+f"(c[1]), "+f"(c[2]), "+f"(c[3])
        : "r"(a[0]), "r"(a[1]), "r"(a[2]), "r"(a[3]), "r"(b0), "r"(b1));
}
__device__ __forceinline__ void mma_fp16(float* c, const uint32_t* a,
                                         uint32_t b0, uint32_t b1) {
    asm volatile(
        "mma.sync.aligned.m16n8k16.row.col.f32.f16.f16.f32 "
        "{%0,%1,%2,%3}, {%4,%5,%6,%7}, {%8,%9}, {%0,%1,%2,%3};"
        : "+f"(c[0]), "+f"(c[1]), "+f"(c[2]), "+f"(c[3])
        : "r"(a[0]), "r"(a[1]), "r"(a[2]), "r"(a[3]), "r"(b0), "r"(b1));
}

__device__ __forceinline__ uint32_t pack_bf16(float a, float b) {
    const unsigned short ha = __bfloat16_as_ushort(__float2bfloat16(a));
    const unsigned short hb = __bfloat16_as_ushort(__float2bfloat16(b));
    return (uint32_t)ha | ((uint32_t)hb << 16);
}
__device__ __forceinline__ uint32_t pack_f16(float a, float b) {
    const __half2 h = __floats2half2_rn(a, b);   // x=a (lo), y=b (hi)
    return *(const uint32_t*)&h;
}
__device__ __forceinline__ float bf_hi_res(float v, float& res) {
    const __nv_bfloat16 h = __float2bfloat16(v);
    res = v - __bfloat162float(h);
    return __bfloat162float(h);
}

// ---------------------------------------------------------------------------
// A split: A[1024,64] f32 -> g_Ah/g_Al bf16
// ---------------------------------------------------------------------------
__global__ __launch_bounds__(256) void asplit_kernel(const float* __restrict__ A) {
    const int i = blockIdx.x * 256 + threadIdx.x;  // float4 idx, 16384 total
    float4 v = ((const float4*)A)[i];
    float r0, r1, r2, r3;
    const float h0 = bf_hi_res(v.x, r0), h1 = bf_hi_res(v.y, r1);
    const float h2 = bf_hi_res(v.z, r2), h3 = bf_hi_res(v.w, r3);
    uint2 ph, pl;
    ph.x = pack_bf16(h0, h1); ph.y = pack_bf16(h2, h3);
    pl.x = pack_bf16(r0, r1); pl.y = pack_bf16(r2, r3);
    ((uint2*)g_Ah)[i] = ph;
    ((uint2*)g_Al)[i] = pl;
}

// ---------------------------------------------------------------------------
// Tensor-core projection, pipelined (unchanged from rounds 8-10)
// ---------------------------------------------------------------------------
__global__ __launch_bounds__(256) void proj_tc_kernel(const float* __restrict__ xtr,
                                                      const float* __restrict__ xt) {
    __shared__ __align__(1024) char psm[65536];
    const uint32_t sb = smem_u32(psm);

    const bool isQ = (blockIdx.x >= 64);
    const float* __restrict__ X = isQ ? xt : xtr;
    float* C = isQ ? g_Q : g_K;
    const int mbase = (blockIdx.x & 63) * 128;

    const int tid = threadIdx.x;
    const int wid = tid >> 5;
    const int lane = tid & 31;
    const int l7 = lane & 7, l15 = lane & 15;
    const int g = lane >> 2, t = lane & 3;
    const int ab = lane >> 3;
    const int arow = l7 + ((ab & 1) << 3);
    const int acs = ab >> 1;
    const int nn_inc = (lane >> 4) & 1;
    const int wr = wid * 16;

    const int xrow = tid >> 1;
    const int xc0 = (tid & 1) * 4;
    const float* xsrc = X + (size_t)(mbase + xrow) * DIN + xc0 * 8;

    float4 xv[4][2];
#pragma unroll
    for (int c = 0; c < 4; ++c) {
        xv[c][0] = *(const float4*)(xsrc + c * 8);
        xv[c][1] = *(const float4*)(xsrc + c * 8 + 4);
    }

    {
        const uint32_t abuf = sb + 32768;
        for (int c = tid; c < 512; c += 256) {
            const int k = c >> 3, dc = c & 7;
            const uint32_t swo = (uint32_t)(k * 128 + ((dc ^ (k & 7)) << 4));
            cp16(abuf + swo, g_Ah + (size_t)k * LD + dc * 8);
            cp16(abuf + 8192 + swo, g_Al + (size_t)k * LD + dc * 8);
        }
        CP_COMMIT;
    }

    float oacc[8][4];
#pragma unroll
    for (int n = 0; n < 8; ++n)
#pragma unroll
        for (int j = 0; j < 4; ++j) oacc[n][j] = 0.0f;

    for (int kt = 0; kt < 16; ++kt) {
        const uint32_t abuf = sb + 32768 + (uint32_t)(kt & 1) * 16384;

#pragma unroll
        for (int c = 0; c < 4; ++c) {
            const int dc = xc0 + c;
            float r0, r1, r2, r3, r4, r5, r6, r7;
            const float h0 = bf_hi_res(xv[c][0].x, r0), h1 = bf_hi_res(xv[c][0].y, r1);
            const float h2 = bf_hi_res(xv[c][0].z, r2), h3 = bf_hi_res(xv[c][0].w, r3);
            const float h4 = bf_hi_res(xv[c][1].x, r4), h5 = bf_hi_res(xv[c][1].y, r5);
            const float h6 = bf_hi_res(xv[c][1].z, r6), h7 = bf_hi_res(xv[c][1].w, r7);
            uint4 ph, pl;
            ph.x = pack_bf16(h0, h1); ph.y = pack_bf16(h2, h3);
            ph.z = pack_bf16(h4, h5); ph.w = pack_bf16(h6, h7);
            pl.x = pack_bf16(r0, r1); pl.y = pack_bf16(r2, r3);
            pl.z = pack_bf16(r4, r5); pl.w = pack_bf16(r6, r7);
            const uint32_t swo = (uint32_t)(xrow * 128 + ((dc ^ (xrow & 7)) << 4));
            *(uint4*)(psm + swo) = ph;
            *(uint4*)(psm + 16384 + swo) = pl;
        }

        if (kt + 1 < 16) {
            const uint32_t anext = sb + 32768 + (uint32_t)((kt + 1) & 1) * 16384;
            const int k0n = (kt + 1) * 64;
            for (int c = tid; c < 512; c += 256) {
                const int k = c >> 3, dc = c & 7;
                const uint32_t swo = (uint32_t)(k * 128 + ((dc ^ (k & 7)) << 4));
                cp16(anext + swo, g_Ah + (size_t)(k0n + k) * LD + dc * 8);
                cp16(anext + 8192 + swo, g_Al + (size_t)(k0n + k) * LD + dc * 8);
            }
            CP_COMMIT;
#pragma unroll
            for (int c = 0; c < 4; ++c) {
                xv[c][0] = *(const float4*)(xsrc + k0n + c * 8);
                xv[c][1] = *(const float4*)(xsrc + k0n + c * 8 + 4);
            }
            CP_WAIT1;
        } else {
            CP_WAIT0;
        }
        __syncthreads();

        const uint32_t xa_base = sb + (uint32_t)((wr + arow) * 128);
#pragma unroll
        for (int ks = 0; ks < 4; ++ks) {
            uint32_t axh[4], axl[4];
            const uint32_t qaddr = xa_base + (uint32_t)((((ks << 1) + acs) ^ l7) << 4);
            ldsm_x4(axh, qaddr);
            ldsm_x4(axl, qaddr + 16384);
            const uint32_t brow = abuf + (uint32_t)((ks * 16 + l15) * 128);
#pragma unroll
            for (int n = 0; n < 8; n += 2) {
                const uint32_t baddr = brow + (uint32_t)(((n + nn_inc) ^ l7) << 4);
                uint32_t bh[4], bl[4];
                ldsm_x4t(bh, baddr);
                ldsm_x4t(bl, baddr + 8192);
                mma_bf16(oacc[n], axh, bh[0], bh[1]);
                mma_bf16(oacc[n], axl, bh[0], bh[1]);
                mma_bf16(oacc[n], axh, bl[0], bl[1]);
                mma_bf16(oacc[n + 1], axh, bh[2], bh[3]);
                mma_bf16(oacc[n + 1], axl, bh[2], bh[3]);
                mma_bf16(oacc[n + 1], axh, bl[2], bl[3]);
            }
        }
        __syncthreads();
    }

    const int row0 = mbase + wr + g;
#pragma unroll
    for (int n = 0; n < 8; ++n) {
        *(float2*)(C + (size_t)row0 * LD + n * 8 + 2 * t) =
            make_float2(oacc[n][0], oacc[n][1]);
        *(float2*)(C + (size_t)(row0 + 8) * LD + n * 8 + 2 * t) =
            make_float2(oacc[n][2], oacc[n][3]);
    }
}

// ---------------------------------------------------------------------------
__global__ __launch_bounds__(256) void colmean_kernel() {
    __shared__ float red[256];
    const int l = blockIdx.x;
    float s = 0.0f;
    for (int r = threadIdx.x; r < NTR; r += 256) s += g_K[(size_t)r * LD + l];
    red[threadIdx.x] = s;
    __syncthreads();
    for (int off = 128; off > 0; off >>= 1) {
        if (threadIdx.x < off) red[threadIdx.x] += red[threadIdx.x + off];
        __syncthreads();
    }
    if (threadIdx.x == 0) g_muA[l] = red[0] * (1.0f / (float)NTR);
}

// ---------------------------------------------------------------------------
// center + bf16 split of Q/K
// ---------------------------------------------------------------------------
__global__ __launch_bounds__(256) void split_qk_kernel() {
    int i = blockIdx.x * 256 + threadIdx.x;
    const bool isQ = (i >= 131072);
    const float* src = isQ ? g_Q : g_K;
    __nv_bfloat16* dh = isQ ? g_Qh : g_Kh;
    __nv_bfloat16* dl = isQ ? g_Ql : g_Kl;
    const int j = isQ ? i - 131072 : i;
    float4 v = ((const float4*)src)[j];
    const int l = (j * 4) & 63;
    v.x -= g_muA[l + 0];
    v.y -= g_muA[l + 1];
    v.z -= g_muA[l + 2];
    v.w -= g_muA[l + 3];
    float r0, r1, r2, r3;
    const float h0 = bf_hi_res(v.x, r0), h1 = bf_hi_res(v.y, r1);
    const float h2 = bf_hi_res(v.z, r2), h3 = bf_hi_res(v.w, r3);
    uint2 ph, pl;
    ph.x = pack_bf16(h0, h1); ph.y = pack_bf16(h2, h3);
    pl.x = pack_bf16(r0, r1); pl.y = pack_bf16(r2, r3);
    ((uint2*)dh)[j] = ph;
    ((uint2*)dl)[j] = pl;
}

// ---------------------------------------------------------------------------
// V convert to fp16 (single, no split): ytr [8192,128] f32 -> g_Vf
// ---------------------------------------------------------------------------
__global__ __launch_bounds__(256) void vconv_kernel(const float* __restrict__ ytr) {
    const int i = blockIdx.x * 256 + threadIdx.x;  // float4 idx, 262144 total
    float4 v = ((const float4*)ytr)[i];
    uint2 p;
    p.x = pack_f16(v.x, v.y);
    p.y = pack_f16(v.z, v.w);
    ((uint2*)g_Vf)[i] = p;
}

// ---------------------------------------------------------------------------
// flash kernel — K double-buffered (2x32KB bf16 hi/lo), V single fp16 (32KB).
// Online row-max softmax; PV = single fp16 mma term. smem 128KB.
// V smem layout identical to round-10 geometry: 256B rows, 16 chunks of 16B,
// swizzle (chunk ^ (key&7)) << 4 on both store and ldmatrix sides.
// ---------------------------------------------------------------------------
#define FB_QH 0
#define FB_QL 16384
#define FB_KB 32768
// K buf b at FB_KB + b*32768: KH +0, KL +16384
#define FB_V  98304
#define FSM_BYTES 131072

extern __shared__ char fsm[];

__device__ __forceinline__ void load_K_tile(uint32_t sb, int buf, int kb, int tid) {
    const uint32_t base = sb + FB_KB + (uint32_t)buf * 32768;
    for (int c = tid; c < 1024; c += 256) {
        const int key = c >> 3, dc = c & 7;
        const uint32_t dst = base + key * 128 + ((dc ^ (key & 7)) << 4);
        const size_t gk = ((size_t)(kb + key) << 6) + dc * 8;
        cp16(dst, g_Kh + gk);
        cp16(dst + 16384, g_Kl + gk);
    }
}

__global__ __launch_bounds__(256) void flash_mma_kernel() {
    const int tid = threadIdx.x;
    const int wid = tid >> 5;
    const int lane = tid & 31;
    const int g = lane >> 2;
    const int t = lane & 3;
    const int qblk = blockIdx.x >> 1;
    const int half = blockIdx.x & 1;
    const int qbase = qblk * 128;
    const int wr = wid * 16;
    const uint32_t sb = smem_u32(fsm);

    // ---- prologue: Q tile + K tile 0 in one cp group
    for (int c = tid; c < 1024; c += 256) {
        const int row = c >> 3, dc = c & 7;
        const uint32_t dst = sb + FB_QH + row * 128 + ((dc ^ (row & 7)) << 4);
        const size_t gq = ((size_t)(qbase + row) << 6) + dc * 8;
        cp16(dst, g_Qh + gq);
        cp16(dst + (FB_QL - FB_QH), g_Ql + gq);
    }
    load_K_tile(sb, 0, half * 4096, tid);
    CP_COMMIT;

    const int l7 = lane & 7, l15 = lane & 15;
    const int ab = lane >> 3;
    const int arow = l7 + ((ab & 1) << 3);
    const int acs = ab >> 1;
    const int kcb = (lane >> 3) & 1;
    const int nn_inc = (lane >> 4) & 1;
    const uint32_t qa_base = sb + FB_QH + (uint32_t)(wr + arow) * 128;
    const uint32_t va_base = sb + FB_V + (uint32_t)l15 * 256;

    float oacc[16][4];
#pragma unroll
    for (int n = 0; n < 16; ++n)
#pragma unroll
        for (int j = 0; j < 4; ++j) oacc[n][j] = 0.0f;
    float rlo = 0.0f, rhi = 0.0f;
    float m0 = -1e30f, m1 = -1e30f;

    for (int jt = 0; jt < 32; ++jt) {
        const int kb = (half * 32 + jt) * 128;
        const uint32_t kbase = sb + FB_KB + (uint32_t)(jt & 1) * 32768;

        CP_WAIT0;          // K(jt) (and Q on first iter) resident
        __syncthreads();   // guards V buffer: all PV(jt-1) reads done

        // ---- V(jt) fp16 load, overlapped with QK compute
        //      row = 256B, chunk dc in 0..15 of 16B (= 8 fp16 dy values)
        for (int c = tid; c < 2048; c += 256) {
            const int key = c >> 4, dc = c & 15;
            const uint32_t dst = sb + FB_V + key * 256 + ((dc ^ (key & 7)) << 4);
            cp16(dst, g_Vf + ((size_t)(kb + key) << 7) + dc * 8);
        }
        CP_COMMIT;

        // ---- S = Q K^T : bf16 3-term, x4 ldmatrix
        float sacc[16][4];
#pragma unroll
        for (int n = 0; n < 16; ++n)
#pragma unroll
            for (int j = 0; j < 4; ++j) sacc[n][j] = 0.0f;

#pragma unroll
        for (int ks = 0; ks < 4; ++ks) {
            uint32_t aqh[4], aql[4];
            const uint32_t qaddr =
                qa_base + (uint32_t)((((ks << 1) + acs) ^ l7) << 4);
            ldsm_x4(aqh, qaddr);
            ldsm_x4(aql, qaddr + (FB_QL - FB_QH));
            const uint32_t ksw = (uint32_t)((((ks << 1) + kcb) ^ l7) << 4);
#pragma unroll
            for (int n = 0; n < 16; n += 2) {
                const uint32_t kaddr =
                    kbase + (uint32_t)((((n + nn_inc) << 3) + l7) * 128) + ksw;
                uint32_t bh[4], bl[4];
                ldsm_x4(bh, kaddr);
                ldsm_x4(bl, kaddr + 16384);
                mma_bf16(sacc[n], aqh, bh[0], bh[1]);
                mma_bf16(sacc[n], aql, bh[0], bh[1]);
                mma_bf16(sacc[n], aqh, bl[0], bl[1]);
                mma_bf16(sacc[n + 1], aqh, bh[2], bh[3]);
                mma_bf16(sacc[n + 1], aql, bh[2], bh[3]);
                mma_bf16(sacc[n + 1], aqh, bl[2], bl[3]);
            }
        }

        // ---- prefetch K(jt+1) (overlaps softmax+PV)
        if (jt + 1 < 32) {
            load_K_tile(sb, (jt + 1) & 1, kb + 128, tid);
            CP_COMMIT;
            CP_WAIT1;      // V(jt) done; K(jt+1) in flight
        } else {
            CP_WAIT0;      // V(jt) done
        }

        // ---- online softmax: row max, rescale, P = exp(s-m) in fp16
        float tm0 = sacc[0][0], tm1 = sacc[0][2];
#pragma unroll
        for (int n = 0; n < 16; ++n) {
            tm0 = fmaxf(tm0, fmaxf(sacc[n][0], sacc[n][1]));
            tm1 = fmaxf(tm1, fmaxf(sacc[n][2], sacc[n][3]));
        }
        tm0 = fmaxf(tm0, __shfl_xor_sync(0xffffffffu, tm0, 1));
        tm0 = fmaxf(tm0, __shfl_xor_sync(0xffffffffu, tm0, 2));
        tm1 = fmaxf(tm1, __shfl_xor_sync(0xffffffffu, tm1, 1));
        tm1 = fmaxf(tm1, __shfl_xor_sync(0xffffffffu, tm1, 2));
        const float m0n = fmaxf(m0, tm0);
        const float m1n = fmaxf(m1, tm1);
        const float c0 = __expf(m0 - m0n);
        const float c1 = __expf(m1 - m1n);
        m0 = m0n;
        m1 = m1n;
        rlo *= c0;
        rhi *= c1;
#pragma unroll
        for (int n = 0; n < 16; ++n) {
            oacc[n][0] *= c0; oacc[n][1] *= c0;
            oacc[n][2] *= c1; oacc[n][3] *= c1;
        }

        uint32_t pf[16][2];
#pragma unroll
        for (int n = 0; n < 16; ++n) {
            const float e0 = __expf(sacc[n][0] - m0);
            const float e1 = __expf(sacc[n][1] - m0);
            const float e2 = __expf(sacc[n][2] - m1);
            const float e3 = __expf(sacc[n][3] - m1);
            rlo += e0 + e1;
            rhi += e2 + e3;
            pf[n][0] = pack_f16(e0, e1);
            pf[n][1] = pack_f16(e2, e3);
        }
        __syncthreads();   // V writes visible to all warps' ldmatrix

        // ---- O += P V : single fp16 term, x4 trans V loads
#pragma unroll
        for (int s = 0; s < 8; ++s) {
            const uint32_t av[4] = {pf[2 * s][0], pf[2 * s][1],
                                    pf[2 * s + 1][0], pf[2 * s + 1][1]};
            const uint32_t vsb = va_base + (uint32_t)(s << 12);
#pragma unroll
            for (int n = 0; n < 16; n += 2) {
                const uint32_t vaddr = vsb + (uint32_t)(((n + nn_inc) ^ l7) << 4);
                uint32_t vf[4];
                ldsm_x4t(vf, vaddr);
                mma_fp16(oacc[n], av, vf[0], vf[1]);
                mma_fp16(oacc[n + 1], av, vf[2], vf[3]);
            }
        }
    }

    // ---- write partials: O (unnormalized, scaled by e^-m), l, m
    float* Op = g_Opart + (size_t)half * NT * DY;
    const int row0 = qbase + wr + g;
#pragma unroll
    for (int n = 0; n < 16; ++n) {
        *(float2*)(Op + (size_t)row0 * DY + n * 8 + 2 * t) =
            make_float2(oacc[n][0], oacc[n][1]);
        *(float2*)(Op + (size_t)(row0 + 8) * DY + n * 8 + 2 * t) =
            make_float2(oacc[n][2], oacc[n][3]);
    }
    rlo += __shfl_xor_sync(0xffffffffu, rlo, 1);
    rlo += __shfl_xor_sync(0xffffffffu, rlo, 2);
    rhi += __shfl_xor_sync(0xffffffffu, rhi, 1);
    rhi += __shfl_xor_sync(0xffffffffu, rhi, 2);
    if (t == 0) {
        g_lpart[(size_t)half * NT + row0] = rlo;
        g_lpart[(size_t)half * NT + row0 + 8] = rhi;
        g_mpart[(size_t)half * NT + row0] = m0;
        g_mpart[(size_t)half * NT + row0 + 8] = m1;
    }
}

// ---------------------------------------------------------------------------
// combine: out = (O0 e^{m0-M} + O1 e^{m1-M}) / (l0 e^{m0-M} + l1 e^{m1-M})
// ---------------------------------------------------------------------------
__global__ __launch_bounds__(256) void combine_kernel(float* __restrict__ out) {
    const int i = blockIdx.x * 256 + threadIdx.x;  // float4 index, 262144 total
    const int r = (i * 4) >> 7;
    const float ma = g_mpart[r], mb = g_mpart[NT + r];
    const float M = fmaxf(ma, mb);
    const float w0 = __expf(ma - M), w1 = __expf(mb - M);
    const float inv = 1.0f / (g_lpart[r] * w0 + g_lpart[NT + r] * w1);
    float4 a = ((const float4*)g_Opart)[i];
    float4 b = ((const float4*)(g_Opart + (size_t)NT * DY))[i];
    ((float4*)out)[i] =
        make_float4((a.x * w0 + b.x * w1) * inv, (a.y * w0 + b.y * w1) * inv,
                    (a.z * w0 + b.z * w1) * inv, (a.w * w0 + b.w * w1) * inv);
}

// ---------------------------------------------------------------------------
extern "C" void kernel_launch(void* const* d_in, const int* in_sizes, int n_in,
                              void* d_out, int out_size) {
    const float* xtr = (const float*)d_in[0];
    const float* ytr = (const float*)d_in[1];
    const float* xt  = (const float*)d_in[2];
    const float* A   = (const float*)d_in[3];
    float* out = (float*)d_out;

    cudaFuncSetAttribute(flash_mma_kernel,
                         cudaFuncAttributeMaxDynamicSharedMemorySize, FSM_BYTES);

    asplit_kernel<<<64, 256>>>(A);
    proj_tc_kernel<<<128, 256>>>(xtr, xt);
    colmean_kernel<<<64, 256>>>();
    split_qk_kernel<<<1024, 256>>>();
    vconv_kernel<<<1024, 256>>>(ytr);
    flash_mma_kernel<<<128, 256, FSM_BYTES>>>();
    combine_kernel<<<1024, 256>>>(out);
}